// round 5
// baseline (speedup 1.0000x reference)
#include <cuda_runtime.h>
#include <math.h>

// ---------------------------------------------------------------------------
// TextEmbedderLETS on GB300 — R5
//   K1 unchanged (860-CTA fused stream + series branch, ~97us @ ~6.9TB/s).
//   combine_kernel reworked: 160 CTAs, 4 z-groups x 64 d4-lanes per CTA,
//   smem cross-group reduce. R4 combine was 7.7us latency-bound @ 40 CTAs.
// ---------------------------------------------------------------------------

#define BD 256
#define B_SZ 8
#define C_SZ 7
#define T_SZ 45
#define D_SZ 5120
#define D4_SZ (D_SZ / 4)          // 1280
#define S_SZ 4096
#define SPLITS 21
#define STREAM_CTAS (5 * B_SZ * SPLITS)   // 840
#define SERIES_CTAS (D_SZ / BD)           // 20
#define TOTAL_CTAS (STREAM_CTAS + SERIES_CTAS) // 860 < 888 (148*6)

__device__ float4 g_part[SPLITS * B_SZ * D4_SZ];       // mean partial sums (3.44 MB)
__device__ float  g_emb [B_SZ * D_SZ];                 // un-normalized projection
__device__ float  g_ssq_part[SERIES_CTAS * B_SZ];      // per-CTA per-batch sumsq

// ============================================================================
// K1: 840 streaming CTAs (mean partials) + 20 series CTAs (prep + project).
// ============================================================================
__global__ __launch_bounds__(BD, 6) void fused_kernel(
    const float* __restrict__ hs,
    const float* __restrict__ x,
    const float* __restrict__ W,
    const float* __restrict__ bias,
    float* __restrict__ out_xnorm)
{
    const int cta = blockIdx.x;
    const int tid = threadIdx.x;

    if (cta < STREAM_CTAS) {
        // ---------------- streaming: sum a slice of hidden_states -----------
        const int dchunk = cta % 5;
        const int b      = (cta / 5) % B_SZ;
        const int z      = cta / (5 * B_SZ);
        const int d4     = dchunk * BD + tid;

        const int s0 = (int)(((long long)z       * S_SZ) / SPLITS);
        const int s1 = (int)(((long long)(z + 1) * S_SZ) / SPLITS);
        const int rows = s1 - s0;

        const float4* p = reinterpret_cast<const float4*>(hs)
                        + (size_t)b * S_SZ * D4_SZ + (size_t)s0 * D4_SZ + d4;

        float4 a0 = make_float4(0.f, 0.f, 0.f, 0.f);
        float4 a1 = make_float4(0.f, 0.f, 0.f, 0.f);

        int r = 0;
        #pragma unroll 4
        for (; r + 1 < rows; r += 2) {
            float4 v0 = __ldcs(p + (size_t)r       * D4_SZ);
            float4 v1 = __ldcs(p + (size_t)(r + 1) * D4_SZ);
            a0.x += v0.x; a0.y += v0.y; a0.z += v0.z; a0.w += v0.w;
            a1.x += v1.x; a1.y += v1.y; a1.z += v1.z; a1.w += v1.w;
        }
        for (; r < rows; r++) {
            float4 v = __ldcs(p + (size_t)r * D4_SZ);
            a0.x += v.x; a0.y += v.y; a0.z += v.z; a0.w += v.w;
        }

        float4 out;
        out.x = a0.x + a1.x; out.y = a0.y + a1.y;
        out.z = a0.z + a1.z; out.w = a0.w + a1.w;
        g_part[((size_t)z * B_SZ + b) * D4_SZ + d4] = out;
    } else {
        // ---------------- series branch (20 CTAs, hidden under the stream) --
        const int sid = cta - STREAM_CTAS;        // 0..19
        const int d   = sid * BD + tid;           // this CTA's d-range

        __shared__ float sx[B_SZ * C_SZ * T_SZ];  // whole x (10 KB)
        __shared__ float smn[B_SZ * C_SZ], smx[B_SZ * C_SZ];
        __shared__ float s_sm[B_SZ * T_SZ];       // 360 entries
        __shared__ float sred[8][B_SZ];

        const int TOT = B_SZ * C_SZ * T_SZ;       // 2520
        for (int i = tid; i < TOT; i += BD) sx[i] = x[i];
        __syncthreads();

        // per-(b,c) min/max: 56 scans of 45
        if (tid < B_SZ * C_SZ) {
            const float* row = sx + tid * T_SZ;
            float mn = row[0], mx = row[0];
            #pragma unroll
            for (int t = 1; t < T_SZ; t++) {
                float v = row[t];
                mn = fminf(mn, v); mx = fmaxf(mx, v);
            }
            smn[tid] = mn; smx[tid] = mx;
        }
        __syncthreads();

        // CTA 0 alone writes x_normalized (tiny)
        if (sid == 0) {
            for (int i = tid; i < TOT; i += BD) {
                int bc = i / T_SZ;
                float v = sx[i], mn = smn[bc], mx = smx[bc];
                out_xnorm[i] = (mx > mn) ? (v - mn) / (mx - mn) : v;
            }
        }

        // channel means: 360 entries > 256 threads -> strided loop
        for (int i = tid; i < B_SZ * T_SZ; i += BD) {
            int b = i / T_SZ, t = i % T_SZ;
            float s = 0.f;
            #pragma unroll
            for (int c = 0; c < C_SZ; c++)
                s += sx[(b * C_SZ + c) * T_SZ + t];
            s_sm[i] = s * (1.0f / (float)C_SZ);
        }
        __syncthreads();

        // projection: this thread owns column d; batches in 2 groups of 4
        const float bv = bias[d];
        const int warp = tid >> 5, lane = tid & 31;

        #pragma unroll
        for (int g = 0; g < 2; g++) {
            float acc0 = bv, acc1 = bv, acc2 = bv, acc3 = bv;
            const float* m0 = s_sm + (g * 4 + 0) * T_SZ;
            const float* m1 = s_sm + (g * 4 + 1) * T_SZ;
            const float* m2 = s_sm + (g * 4 + 2) * T_SZ;
            const float* m3 = s_sm + (g * 4 + 3) * T_SZ;
            #pragma unroll
            for (int t = 0; t < T_SZ; t++) {
                const float w = W[(size_t)t * D_SZ + d];
                acc0 = fmaf(m0[t], w, acc0);
                acc1 = fmaf(m1[t], w, acc1);
                acc2 = fmaf(m2[t], w, acc2);
                acc3 = fmaf(m3[t], w, acc3);
            }
            g_emb[(size_t)(g * 4 + 0) * D_SZ + d] = acc0;
            g_emb[(size_t)(g * 4 + 1) * D_SZ + d] = acc1;
            g_emb[(size_t)(g * 4 + 2) * D_SZ + d] = acc2;
            g_emb[(size_t)(g * 4 + 3) * D_SZ + d] = acc3;

            const float sq[4] = {acc0 * acc0, acc1 * acc1, acc2 * acc2, acc3 * acc3};
            #pragma unroll
            for (int j = 0; j < 4; j++) {
                float v = sq[j];
                #pragma unroll
                for (int off = 16; off; off >>= 1)
                    v += __shfl_xor_sync(0xffffffffu, v, off);
                if (lane == 0) sred[warp][g * 4 + j] = v;
            }
            __syncthreads();
            if (tid < 4) {
                int b = g * 4 + tid;
                float tot = 0.f;
                #pragma unroll
                for (int w2 = 0; w2 < 8; w2++) tot += sred[w2][b];
                g_ssq_part[sid * B_SZ + b] = tot;
            }
            __syncthreads();
        }
    }
}

// ============================================================================
// K2: combine. grid(20, 8) = 160 CTAs; 256 thr = 4 z-groups x 64 d4 lanes.
//   Each thread sums ~5-6 of the 21 z-partials (coalesced, MLP ~5), then a
//   4-way smem reduce; group 0 adds normalized g_emb and writes out_fused.
// ============================================================================
__global__ __launch_bounds__(BD) void combine_kernel(
    float* __restrict__ out_fused)
{
    const int b    = blockIdx.y;
    const int tid  = threadIdx.x;
    const int zg   = tid >> 6;           // 0..3
    const int j    = tid & 63;           // 0..63
    const int d4   = blockIdx.x * 64 + j;

    __shared__ float4 sacc[3][64];
    __shared__ float  s_inv;

    if (tid == 0) {
        float ssq = 0.f;
        #pragma unroll
        for (int s = 0; s < SERIES_CTAS; s++)
            ssq += g_ssq_part[s * B_SZ + b];
        s_inv = 1.0f / fmaxf(sqrtf(ssq), 1e-12f);
    }

    // z range for this group: boundaries of 21 split 4 ways (5,5,5,6)
    const int z0 = (zg * SPLITS) >> 2;
    const int z1 = ((zg + 1) * SPLITS) >> 2;

    float4 acc = make_float4(0.f, 0.f, 0.f, 0.f);
    #pragma unroll 6
    for (int z = z0; z < z1; z++) {
        float4 v = g_part[((size_t)z * B_SZ + b) * D4_SZ + d4];
        acc.x += v.x; acc.y += v.y; acc.z += v.z; acc.w += v.w;
    }

    if (zg > 0) sacc[zg - 1][j] = acc;
    __syncthreads();

    if (zg == 0) {
        #pragma unroll
        for (int g = 0; g < 3; g++) {
            float4 v = sacc[g][j];
            acc.x += v.x; acc.y += v.y; acc.z += v.z; acc.w += v.w;
        }
        const float inv  = s_inv;
        const float invS = 1.0f / (float)S_SZ;
        const float4 e = reinterpret_cast<const float4*>(g_emb)[(size_t)b * D4_SZ + d4];

        float4 o;
        o.x = fmaf(e.x, inv, acc.x * invS);
        o.y = fmaf(e.y, inv, acc.y * invS);
        o.z = fmaf(e.z, inv, acc.z * invS);
        o.w = fmaf(e.w, inv, acc.w * invS);
        reinterpret_cast<float4*>(out_fused)[(size_t)b * D4_SZ + d4] = o;
    }
}

// ============================================================================
extern "C" void kernel_launch(void* const* d_in, const int* in_sizes, int n_in,
                              void* d_out, int out_size)
{
    const float* x    = (const float*)d_in[0];
    const float* hs   = (const float*)d_in[1];
    const float* W    = (const float*)d_in[2];
    const float* bias = (const float*)d_in[3];

    float* out_fused = (float*)d_out;                       // [B, D]
    float* out_xnorm = (float*)d_out + (size_t)B_SZ * D_SZ; // [B, C, T]

    fused_kernel<<<TOTAL_CTAS, BD>>>(hs, x, W, bias, out_xnorm);
    combine_kernel<<<dim3(D4_SZ / 64, B_SZ), BD>>>(out_fused);
}